// round 14
// baseline (speedup 1.0000x reference)
#include <cuda_runtime.h>
#include <cuda_fp16.h>
#include <cstdint>

// Problem constants: B=8, T=1024, C=768, H=12, HD=64
// All scratch in fp16 (half) except softmax stats.
__device__ __half g_q[6291456];          // [96][1024][64]
__device__ __half g_k[6291456];
__device__ __half g_v[6291456];
__device__ __half g_y[6291456];          // [8192][768]
__device__ __half g_x[6291456];          // [8192][768]
__device__ uint32_t g_wa_p[884736];      // packed w_attn^T [n=2304][k2=384]
__device__ uint32_t g_wp_p[294912];      // packed w_proj^T [n=768][k2=384]

// ---------------------------------------------------------------------------
// helpers
// ---------------------------------------------------------------------------
__device__ __forceinline__ void mma_f16(float* c, const uint32_t* a, const uint32_t* b) {
    asm volatile(
        "mma.sync.aligned.m16n8k16.row.col.f32.f16.f16.f32 "
        "{%0,%1,%2,%3},{%4,%5,%6,%7},{%8,%9},{%0,%1,%2,%3};"
        : "+f"(c[0]), "+f"(c[1]), "+f"(c[2]), "+f"(c[3])
        : "r"(a[0]), "r"(a[1]), "r"(a[2]), "r"(a[3]), "r"(b[0]), "r"(b[1]));
}
#define LDSM_X4(R0, R1, R2, R3, ADDR) \
    asm volatile("ldmatrix.sync.aligned.m8n8.x4.shared.b16 {%0,%1,%2,%3}, [%4];" \
                 : "=r"(R0), "=r"(R1), "=r"(R2), "=r"(R3) : "r"(ADDR))
__device__ __forceinline__ uint32_t smem_u32(const void* p) {
    return (uint32_t)__cvta_generic_to_shared(p);
}
__device__ __forceinline__ uint32_t packh2(float a, float b) {
    __half2 h = __floats2half2_rn(a, b);
    return *(uint32_t*)&h;
}
#define CP_ASYNC16(dst, src) \
    asm volatile("cp.async.cg.shared.global [%0], [%1], 16;\n" :: "r"(dst), "l"(src))
#define CP_COMMIT() asm volatile("cp.async.commit_group;\n")
#define CP_WAIT(N)  asm volatile("cp.async.wait_group %0;\n" :: "n"(N))

// ---------------------------------------------------------------------------
// Kernel 0a: x (float) -> g_x (half).
// ---------------------------------------------------------------------------
__global__ __launch_bounds__(256) void conv_x(const float* __restrict__ x)
{
    long i = (long)blockIdx.x * 256 + threadIdx.x;   // 1572864 float4s
    float4 v = ((const float4*)x)[i];
    uint2 o;
    o.x = packh2(v.x, v.y);
    o.y = packh2(v.z, v.w);
    ((uint2*)g_x)[i] = o;
}

// ---------------------------------------------------------------------------
// Kernel 0b: pack weights TRANSPOSED: Wt[n][k2] = half2(w[2k2][n], w[2k2+1][n]).
// Tiled through smem for coalescing.  Block: 64k x 32n, threads (32,8).
// Destination selected in-kernel (device symbol must not cross host ABI).
// ---------------------------------------------------------------------------
__global__ __launch_bounds__(256) void pack_w_t(
    const float* __restrict__ src, int N, int which)
{
    __shared__ float t[64][33];
    uint32_t* dst = which ? g_wp_p : g_wa_p;
    const int n0 = blockIdx.x * 32, k0 = blockIdx.y * 64;
    const int tx = threadIdx.x, ty = threadIdx.y;
#pragma unroll
    for (int i = 0; i < 64; i += 8)
        t[ty + i][tx] = src[(size_t)(k0 + ty + i) * N + n0 + tx];
    __syncthreads();
#pragma unroll
    for (int j = 0; j < 4; j++) {
        int nl = ty + 8 * j;
        dst[(size_t)(n0 + nl) * 384 + (k0 >> 1) + tx] =
            packh2(t[2 * tx][nl], t[2 * tx + 1][nl]);
    }
}

// ---------------------------------------------------------------------------
// FP16 GEMM core v2: block tile 128x128, 8 warps (2m x 4n), warp tile 64x32,
// K-step 32 halfs, 24 steps, 3-stage cp.async, 1 sync/step,
// ALL fragment loads via ldmatrix.x4.
//   As uint32 [3][128][20]  (A k-pairs, row-major)
//   Bs uint32 [3][128][20]  (B^T: [n][k-pairs] -- same structure as A)
// pitch 20 -> each LDSM 8-row phase hits all 32 banks once (20r%32 bijective).
// Dynamic smem 61440B; 2 CTAs/SM.
// ---------------------------------------------------------------------------
#define GEMM_SMEM_BYTES 61440

#define GEMMH_LOAD(S, CH, APTR, BPTR)                                           \
    _Pragma("unroll")                                                           \
    for (int i = 0; i < 2; i++) {                                               \
        int id = tid + i * 256;                                                 \
        int r = id >> 2, c = id & 3;                                            \
        CP_ASYNC16(smem_u32(&As[S][r][c * 4]),                                  \
                   (APTR) + (size_t)(m0 + r) * 768 + (CH) * 32 + c * 8);        \
    }                                                                           \
    _Pragma("unroll")                                                           \
    for (int i = 0; i < 2; i++) {                                               \
        int id = tid + i * 256;                                                 \
        int r = id >> 2, c = id & 3;                                            \
        CP_ASYNC16(smem_u32(&Bs[S][r][c * 4]),                                  \
                   (BPTR) + (size_t)(n0 + r) * 384 + (CH) * 16 + c * 4);        \
    }                                                                           \
    CP_COMMIT();

#define GEMMH_BODY(APTR, BPTR)                                                  \
    extern __shared__ char smem_raw[];                                          \
    uint32_t (*As)[128][20] = (uint32_t (*)[128][20])smem_raw;                  \
    uint32_t (*Bs)[128][20] = (uint32_t (*)[128][20])(smem_raw + 3 * 128 * 20 * 4); \
    const int tid  = threadIdx.x;                                               \
    const int lane = tid & 31;                                                  \
    const int wid  = tid >> 5;                                                  \
    const int warp_m = wid & 1, warp_n = wid >> 1;                              \
    const int g = lane >> 2, tg = lane & 3;                                     \
    const int m0 = blockIdx.y * 128, n0 = blockIdx.x * 128;                     \
    const uint32_t As_base = smem_u32(smem_raw);                                \
    const uint32_t Bs_base = As_base + 3 * 128 * 20 * 4;                        \
    const uint32_t a_loff = (((lane & 15) * 20) + ((lane >> 4) << 2)) * 4;      \
    const uint32_t b_loff = ((((lane & 7) + ((lane >> 4) << 3)) * 20)           \
                             + (((lane >> 3) & 1) << 2)) * 4;                   \
    float acc[4][4][4] = {};                                                    \
    GEMMH_LOAD(0, 0, APTR, BPTR)                                                \
    GEMMH_LOAD(1, 1, APTR, BPTR)                                                \
    int sidx = 0, pidx = 2;                                                     \
    for (int step = 0; step < 24; step++) {                                     \
        if (step < 23) { CP_WAIT(1); } else { CP_WAIT(0); }                     \
        __syncthreads();                                                        \
        if (step + 2 < 24) {                                                    \
            GEMMH_LOAD(pidx, step + 2, APTR, BPTR)                              \
        }                                                                       \
        const int s = sidx;                                                     \
        const uint32_t a_st = As_base + (s * 128 + warp_m * 64) * 80;           \
        const uint32_t b_st = Bs_base + (s * 128 + warp_n * 32) * 80;           \
        _Pragma("unroll")                                                       \
        for (int ks = 0; ks < 2; ks++) {                                        \
            const int kb = ks * 32;                                             \
            uint32_t afr[4][4], bfr[4][2];                                      \
            _Pragma("unroll")                                                   \
            for (int mt = 0; mt < 4; mt++)                                      \
                LDSM_X4(afr[mt][0], afr[mt][1], afr[mt][2], afr[mt][3],         \
                        a_st + mt * 1280 + kb + a_loff);                        \
            LDSM_X4(bfr[0][0], bfr[0][1], bfr[1][0], bfr[1][1],                 \
                    b_st + kb + b_loff);                                        \
            LDSM_X4(bfr[2][0], bfr[2][1], bfr[3][0], bfr[3][1],                 \
                    b_st + 1280 + kb + b_loff);                                 \
            _Pragma("unroll")                                                   \
            for (int mt = 0; mt < 4; mt++)                                      \
                _Pragma("unroll")                                               \
                for (int nt = 0; nt < 4; nt++)                                  \
                    mma_f16(acc[mt][nt], afr[mt], bfr[nt]);                     \
        }                                                                       \
        sidx = (sidx == 2) ? 0 : sidx + 1;                                      \
        pidx = (pidx == 2) ? 0 : pidx + 1;                                      \
    }

// ---------------------------------------------------------------------------
// Kernel 1: QKV GEMM (M=8192, N=2304, K=768) -> q/k/v half [B,H,T,64].
// ---------------------------------------------------------------------------
__global__ __launch_bounds__(256, 2) void gemm_qkv_h(const float* __restrict__ bias)
{
    GEMMH_BODY(g_x, g_wa_p)

#pragma unroll
    for (int mt = 0; mt < 4; mt++) {
#pragma unroll
        for (int nt = 0; nt < 4; nt++) {
            int n = n0 + warp_n * 32 + nt * 8 + 2 * tg;   // even
            int which = n / 768;
            int c = n - which * 768;
            int hh = c >> 6, d = c & 63;
            uint32_t* dstp = (uint32_t*)((which == 0) ? g_q : (which == 1) ? g_k : g_v);
            float b0 = bias[n], b1 = bias[n + 1];
            int row0 = m0 + warp_m * 64 + mt * 16 + g;
            int bb = row0 >> 10, t0 = row0 & 1023;
            size_t base = ((((size_t)bb * 12 + hh) << 10) + t0) * 32 + (d >> 1);
            dstp[base]          = packh2(acc[mt][nt][0] + b0, acc[mt][nt][1] + b1);
            dstp[base + 8 * 32] = packh2(acc[mt][nt][2] + b0, acc[mt][nt][3] + b1);
        }
    }
}

// ---------------------------------------------------------------------------
// Kernel 3: projection (M=8192, N=768, K=768): g_y(half) @ wp -> fp32 out.
// ---------------------------------------------------------------------------
__global__ __launch_bounds__(256, 2) void gemm_proj_h(
    const float* __restrict__ bias, float* __restrict__ out)
{
    GEMMH_BODY(g_y, g_wp_p)

#pragma unroll
    for (int mt = 0; mt < 4; mt++) {
#pragma unroll
        for (int nt = 0; nt < 4; nt++) {
            int n = n0 + warp_n * 32 + nt * 8 + 2 * tg;
            float b0 = bias[n], b1 = bias[n + 1];
            int row0 = m0 + warp_m * 64 + mt * 16 + g;
            *(float2*)(out + (size_t)row0 * 768 + n) =
                make_float2(acc[mt][nt][0] + b0, acc[mt][nt][1] + b1);
            *(float2*)(out + (size_t)(row0 + 8) * 768 + n) =
                make_float2(acc[mt][nt][2] + b0, acc[mt][nt][3] + b1);
        }
    }
}

// ---------------------------------------------------------------------------
// Kernel 2: causal flash attention, fp16 MMA / fp32 softmax, ldmatrix frags.
// Grid (16, 96), 256 threads = 8 warps (4m x 2n).  Q tile 64 (regs),
// K/V tile 64.  2 CTAs/SM.
//   Sf  fp32 scores [64][68]
//   Ks  uint32 [64][36]   K d-pairs (also Q staging)  -- LDSM, 4r%32 bijective
//   Vp  uint32 [32][72]   V t-pairs                   -- scalar LDS
//   Pp  uint32 [64][36]   P half t-pairs              -- LDSM
// ---------------------------------------------------------------------------
__global__ __launch_bounds__(256, 2) void attn_h_kernel()
{
    __shared__ float Sf[64][68];
    __shared__ uint32_t Ks[64][36];
    __shared__ uint32_t Vp[32][72];
    __shared__ uint32_t Pp[64][36];
    __shared__ float s_m[64], s_l[64], s_f[64];

    const int tid = threadIdx.x;
    const int lane = tid & 31;
    const int wid = tid >> 5;
    const int warp_m = wid & 3, warp_n = wid >> 2;
    const int g = lane >> 2, tg = lane & 3;
    const int qi = blockIdx.x, bh = blockIdx.y;
    const int q0 = qi * 64;
    const __half* qb = g_q + (size_t)bh * 65536;
    const __half* kb = g_k + (size_t)bh * 65536;
    const __half* vb = g_v + (size_t)bh * 65536;
    const int mr = warp_m * 16;

    const uint32_t Ks_base = smem_u32(&Ks[0][0]);
    const uint32_t Pp_base = smem_u32(&Pp[0][0]);
    // A-style lane offset (pitch 36 uint32 = 144B/row)
    const uint32_t a36_loff = (((lane & 15) * 36) + ((lane >> 4) << 2)) * 4;
    // B-style lane offset for Ks (rows = n)
    const uint32_t b36_loff = ((((lane & 7) + ((lane >> 4) << 3)) * 36)
                               + (((lane >> 3) & 1) << 2)) * 4;

    // Stage Q (half) into Ks, hoist this warp's A-fragments via LDSM.
#pragma unroll
    for (int r = 0; r < 2; r++) {
        int id = tid + r * 256;
        int q = id >> 3, c = id & 7;
        *(uint4*)&Ks[q][c * 4] = *(const uint4*)(qb + (size_t)(q0 + q) * 64 + c * 8);
    }
    if (tid < 64) { s_m[tid] = -1e30f; s_l[tid] = 0.0f; }
    __syncthreads();

    uint32_t qfr[4][4];
#pragma unroll
    for (int ks = 0; ks < 4; ks++)
        LDSM_X4(qfr[ks][0], qfr[ks][1], qfr[ks][2], qfr[ks][3],
                Ks_base + mr * 144 + ks * 32 + a36_loff);

    float acc_o[4][4] = {};

    const int ktiles = qi + 1;
    for (int kt = 0; kt < ktiles; kt++) {
        const int k0 = kt * 64;
        const bool diag = (kt == qi);

        __syncthreads();   // qfr hoisted / prior tile reads done
        // load K tile (d-pairs natural)
#pragma unroll
        for (int r = 0; r < 2; r++) {
            int id = tid + r * 256;
            int t = id >> 3, c = id & 7;
            *(uint4*)&Ks[t][c * 4] = *(const uint4*)(kb + (size_t)(k0 + t) * 64 + c * 8);
        }
        // load V tile, pack to t-pairs via byte_perm
#pragma unroll
        for (int j = 0; j < 4; j++) {
            int id = tid + j * 256;
            int i = id >> 5, d2 = id & 31;
            uint32_t r0 = *(const uint32_t*)(vb + (size_t)(k0 + 2 * i) * 64 + 2 * d2);
            uint32_t r1 = *(const uint32_t*)(vb + (size_t)(k0 + 2 * i + 1) * 64 + 2 * d2);
            Vp[i][2 * d2]     = __byte_perm(r0, r1, 0x5410);
            Vp[i][2 * d2 + 1] = __byte_perm(r0, r1, 0x7632);
        }
        __syncthreads();

        // ---- S = Q K^T (B-frags via LDSM) ----
        float acc_s[4][4] = {};
#pragma unroll
        for (int ks = 0; ks < 4; ks++) {
            const int kb4 = ks * 32;
            uint32_t bfr[4][2];
            LDSM_X4(bfr[0][0], bfr[0][1], bfr[1][0], bfr[1][1],
                    Ks_base + (warp_n * 32) * 144 + kb4 + b36_loff);
            LDSM_X4(bfr[2][0], bfr[2][1], bfr[3][0], bfr[3][1],
                    Ks_base + (warp_n * 32 + 16) * 144 + kb4 + b36_loff);
#pragma unroll
            for (int nt = 0; nt < 4; nt++)
                mma_f16(acc_s[nt], qfr[ks], bfr[nt]);
        }
        // mask + scale -> Sf (fp32)
#pragma unroll
        for (int nt = 0; nt < 4; nt++) {
            const int nc = warp_n * 32 + nt * 8;
#pragma unroll
            for (int e = 0; e < 4; e++) {
                int row = mr + g + (e >> 1) * 8;
                int col = nc + 2 * tg + (e & 1);
                float v = acc_s[nt][e] * 0.125f;
                if (diag && col > row) v = -1e30f;
                Sf[row][col] = v;
            }
        }
        __syncthreads();

        // ---- online softmax: 4 threads/row, write P as half t-pairs ----
        {
            const int row = tid >> 2, sub = tid & 3;
            float mold = s_m[row];
            float mt = mold;
            float vals[16];
#pragma unroll
            for (int j = 0; j < 16; j++) {
                vals[j] = Sf[row][sub * 16 + j];
                mt = fmaxf(mt, vals[j]);
            }
            mt = fmaxf(mt, __shfl_xor_sync(0xffffffffu, mt, 1));
            mt = fmaxf(mt, __shfl_xor_sync(0xffffffffu, mt, 2));
            float ls = 0.0f;
#pragma unroll
            for (int j = 0; j < 16; j++) {
                vals[j] = __expf(vals[j] - mt);
                ls += vals[j];
            }
#pragma unroll
            for (int j2 = 0; j2 < 8; j2++)
                Pp[row][sub * 8 + j2] = packh2(vals[2 * j2], vals[2 * j2 + 1]);
            ls += __shfl_xor_sync(0xffffffffu, ls, 1);
            ls += __shfl_xor_sync(0xffffffffu, ls, 2);
            if (sub == 0) {
                float f = __expf(mold - mt);
                s_m[row] = mt;
                s_l[row] = s_l[row] * f + ls;
                s_f[row] = f;
            }
        }
        __syncthreads();

        // ---- rescale O, accumulate P @ V (P A-frags via LDSM) ----
        float f0 = s_f[mr + g], f1 = s_f[mr + g + 8];
#pragma unroll
        for (int nt = 0; nt < 4; nt++) {
            acc_o[nt][0] *= f0; acc_o[nt][1] *= f0;
            acc_o[nt][2] *= f1; acc_o[nt][3] *= f1;
        }
#pragma unroll
        for (int ts = 0; ts < 4; ts++) {
            const int kk = ts * 8;
            uint32_t afr[4];
            LDSM_X4(afr[0], afr[1], afr[2], afr[3],
                    Pp_base + mr * 144 + ts * 32 + a36_loff);
#pragma unroll
            for (int nt = 0; nt < 4; nt++) {
                const int nc = warp_n * 32 + nt * 8;
                uint32_t bfr[2];
                bfr[0] = Vp[kk + tg][nc + g];
                bfr[1] = Vp[kk + tg + 4][nc + g];
                mma_f16(acc_o[nt], afr, bfr);
            }
        }
    }

    // ---- epilogue: normalize, write g_y (half) in [B,T,C] layout ----
    const int b = bh / 12, h = bh - b * 12;
    float inv0 = 1.0f / s_l[mr + g];
    float inv1 = 1.0f / s_l[mr + g + 8];
    const int t0 = q0 + mr + g, t1 = t0 + 8;
#pragma unroll
    for (int nt = 0; nt < 4; nt++) {
        int col = warp_n * 32 + nt * 8 + 2 * tg;   // even
        uint32_t* d0 = (uint32_t*)(g_y + ((size_t)(b * 1024 + t0)) * 768 + h * 64 + col);
        uint32_t* d1 = (uint32_t*)(g_y + ((size_t)(b * 1024 + t1)) * 768 + h * 64 + col);
        *d0 = packh2(acc_o[nt][0] * inv0, acc_o[nt][1] * inv0);
        *d1 = packh2(acc_o[nt][2] * inv1, acc_o[nt][3] * inv1);
    }
}

// ---------------------------------------------------------------------------
extern "C" void kernel_launch(void* const* d_in, const int* in_sizes, int n_in,
                              void* d_out, int out_size)
{
    const float* x      = (const float*)d_in[0];
    const float* w_attn = (const float*)d_in[1];
    const float* b_attn = (const float*)d_in[2];
    const float* w_proj = (const float*)d_in[3];
    const float* b_proj = (const float*)d_in[4];
    float* out = (float*)d_out;

    static bool attr_set = false;
    if (!attr_set) {
        cudaFuncSetAttribute(gemm_qkv_h,
            cudaFuncAttributeMaxDynamicSharedMemorySize, GEMM_SMEM_BYTES);
        cudaFuncSetAttribute(gemm_proj_h,
            cudaFuncAttributeMaxDynamicSharedMemorySize, GEMM_SMEM_BYTES);
        attr_set = true;
    }

    conv_x<<<6144, 256>>>(x);
    pack_w_t<<<dim3(72, 12), dim3(32, 8)>>>(w_attn, 2304, 0);
    pack_w_t<<<dim3(24, 12), dim3(32, 8)>>>(w_proj, 768, 1);
    gemm_qkv_h<<<dim3(18, 64), 256, GEMM_SMEM_BYTES>>>(b_attn);
    attn_h_kernel<<<dim3(16, 96), 256>>>();
    gemm_proj_h<<<dim3(6, 64), 256, GEMM_SMEM_BYTES>>>(b_proj, out);
}